// round 1
// baseline (speedup 1.0000x reference)
#include <cuda_runtime.h>
#include <math.h>
#include <cstdint>

#define BB 2
#define LL 1024
#define DM 768
#define DI 1536
#define DS 16
#define DD 48
#define NTOK (BB*LL)
#define XPE 80   // D_DELTA + 2*D_STATE

// ---------------- scratch (static device globals; no allocation) ----------------
__device__ float g_xn[NTOK*DM];          // rmsnorm output
__device__ float g_xz[NTOK*2*DI];        // in_proj output (xi | z)
__device__ float g_xc[NTOK*DI];          // conv+silu output
__device__ float g_dbc[NTOK*XPE];        // xproj output (delta_raw | B | C)
__device__ float g_delta[NTOK*DI];       // softplus(dt proj)
__device__ float g_y[NTOK*DI];           // scan output (gated)

__device__ __forceinline__ float sigmoidf_(float x){ return 1.f/(1.f+__expf(-x)); }
__device__ __forceinline__ float softplus_(float v){ return v > 20.f ? v : log1pf(expf(v)); }

// ---------------- rmsnorm: one block per token ----------------
__global__ void rmsnorm_kernel(const float* __restrict__ x, const float* __restrict__ w,
                               float* __restrict__ out)
{
    int tok = blockIdx.x;
    int tid = threadIdx.x;  // 256
    const float* xr = x + (size_t)tok*DM;
    float v0 = xr[tid], v1 = xr[tid+256], v2 = xr[tid+512];
    float s = v0*v0 + v1*v1 + v2*v2;
    #pragma unroll
    for (int o=16;o>0;o>>=1) s += __shfl_xor_sync(0xffffffffu, s, o);
    __shared__ float red[8];
    if ((tid&31)==0) red[tid>>5] = s;
    __syncthreads();
    float tot = red[0]+red[1]+red[2]+red[3]+red[4]+red[5]+red[6]+red[7];
    float r = rsqrtf(tot * (1.f/768.f) + 1e-5f);
    float* o = out + (size_t)tok*DM;
    o[tid]     = w[tid]     * v0 * r;
    o[tid+256] = w[tid+256] * v1 * r;
    o[tid+512] = w[tid+512] * v2 * r;
}

// ---------------- tiled fp32 GEMM: C[M,N] (epi)= A[M,K] * B[N,K]^T ----------------
// 128x64 block tile, K-step 16, 256 threads, 8x4 register tile.
// EPI: 0 = plain store, 1 = softplus(acc + bias[n]), 2 = residual accumulate (C += acc)
template<int EPI>
__global__ void __launch_bounds__(256)
gemm_nt(const float* __restrict__ A, const float* __restrict__ B,
        const float* __restrict__ bias, float* __restrict__ C,
        int M, int N, int K, int lda, int ldb, int ldc)
{
    __shared__ float As[16][132];   // padded to soften STS conflicts
    __shared__ float Bs[16][68];
    int tid = threadIdx.x;
    int m0 = blockIdx.y * 128;
    int n0 = blockIdx.x * 64;
    int tx = tid & 15, ty = tid >> 4;

    float acc[8][4];
    #pragma unroll
    for (int i=0;i<8;i++)
        #pragma unroll
        for (int j=0;j<4;j++) acc[i][j]=0.f;

    int ar = tid >> 2;           // 0..63
    int kq = (tid & 3) * 4;      // 0,4,8,12

    for (int k0=0;k0<K;k0+=16) {
        #pragma unroll
        for (int i=0;i<2;i++){
            int r = ar + i*64;
            float4 v = *(const float4*)(A + (size_t)(m0+r)*lda + k0 + kq);
            As[kq+0][r]=v.x; As[kq+1][r]=v.y; As[kq+2][r]=v.z; As[kq+3][r]=v.w;
        }
        {
            int r = ar;
            float4 v = make_float4(0.f,0.f,0.f,0.f);
            if (n0 + r < N) v = *(const float4*)(B + (size_t)(n0+r)*ldb + k0 + kq);
            Bs[kq+0][r]=v.x; Bs[kq+1][r]=v.y; Bs[kq+2][r]=v.z; Bs[kq+3][r]=v.w;
        }
        __syncthreads();
        #pragma unroll
        for (int k=0;k<16;k++){
            float4 b  = *(const float4*)&Bs[k][tx*4];
            float4 a0 = *(const float4*)&As[k][ty*8];
            float4 a1 = *(const float4*)&As[k][ty*8+4];
            float av[8] = {a0.x,a0.y,a0.z,a0.w,a1.x,a1.y,a1.z,a1.w};
            float bv[4] = {b.x,b.y,b.z,b.w};
            #pragma unroll
            for (int i=0;i<8;i++)
                #pragma unroll
                for (int j=0;j<4;j++)
                    acc[i][j] = fmaf(av[i], bv[j], acc[i][j]);
        }
        __syncthreads();
    }

    int col = n0 + tx*4;
    if (col < N) {
        float b0=0,b1=0,b2=0,b3=0;
        if (EPI==1){ b0=bias[col]; b1=bias[col+1]; b2=bias[col+2]; b3=bias[col+3]; }
        #pragma unroll
        for (int i=0;i<8;i++){
            int row = m0 + ty*8 + i;
            float* cp = C + (size_t)row*ldc + col;
            float4 o;
            o.x=acc[i][0]; o.y=acc[i][1]; o.z=acc[i][2]; o.w=acc[i][3];
            if (EPI==1){
                o.x = softplus_(o.x + b0); o.y = softplus_(o.y + b1);
                o.z = softplus_(o.z + b2); o.w = softplus_(o.w + b3);
            } else if (EPI==2){
                float4 old = *(const float4*)cp;
                o.x+=old.x; o.y+=old.y; o.z+=old.z; o.w+=old.w;
            }
            *(float4*)cp = o;
        }
    }
}

// ---------------- causal depthwise conv (K=4) + SiLU ----------------
__global__ void conv_silu_kernel(const float* __restrict__ xz, const float* __restrict__ cw,
                                 const float* __restrict__ cb, float* __restrict__ xc)
{
    int idx = blockIdx.x*blockDim.x + threadIdx.x;   // NTOK*DI total
    int d = idx % DI;
    int tok = idx / DI;
    int l = tok % LL, b = tok / LL;
    float acc = cb[d];
    #pragma unroll
    for (int j=0;j<4;j++){
        int li = l - 3 + j;
        if (li >= 0) acc = fmaf(cw[d*4+j], xz[(size_t)(b*LL+li)*(2*DI) + d], acc);
    }
    xc[idx] = acc * sigmoidf_(acc);
}

// ---------------- selective scan ----------------
// 16 lanes per (b,d) channel (one per state n). dA/dBx recomputed on the fly.
// Chunked SMEM staging (64 steps), double-buffered; LDGs for chunk c+1 are issued
// into registers before computing chunk c, hiding global latency.
// Fused epilogue: out = (y + D*x) * silu(z).
#define ST 64
__global__ void __launch_bounds__(256)
scan_kernel(const float* __restrict__ delta, const float* __restrict__ xc,
            const float* __restrict__ dbc, const float* __restrict__ xz,
            const float* __restrict__ A_log, const float* __restrict__ Dp,
            float* __restrict__ out)
{
    __shared__ float s_delta[2][ST][16];
    __shared__ float s_x[2][ST][16];
    __shared__ float s_z[2][ST][16];
    __shared__ float s_B[2][ST][16];
    __shared__ float s_C[2][ST][16];

    int tid = threadIdx.x;
    int g   = blockIdx.x*16 + (tid>>4);    // global (b,d) group
    int n   = tid & 15;                     // state index
    int b   = g / DI;
    int d   = g % DI;
    int d0  = (blockIdx.x*16) % DI;         // block's base d (whole block shares b)

    float An = -expf(A_log[d*DS + n]);
    float Dd = Dp[d];

    // loader lane mapping: fixed channel-col lj, 4 time rows per array
    int lj = tid & 15, lt0 = tid >> 4;

    float r_delta[4], r_x[4], r_z[4], r_B[4], r_C[4];

    const int NC = LL/ST;   // 16
    // prefetch chunk 0
    {
        int t0 = 0;
        #pragma unroll
        for (int k=0;k<4;k++){
            int t = lt0 + k*16;
            int tok = b*LL + t0 + t;
            r_delta[k] = delta[(size_t)tok*DI + d0 + lj];
            r_x[k]     = xc[(size_t)tok*DI + d0 + lj];
            r_z[k]     = xz[(size_t)tok*(2*DI) + DI + d0 + lj];
            r_B[k]     = dbc[(size_t)tok*XPE + DD + lj];
            r_C[k]     = dbc[(size_t)tok*XPE + DD + DS + lj];
        }
    }

    float h = 0.f;
    for (int c=0;c<NC;c++){
        int buf = c & 1;
        #pragma unroll
        for (int k=0;k<4;k++){
            int t = lt0 + k*16;
            s_delta[buf][t][lj]=r_delta[k];
            s_x[buf][t][lj]=r_x[k];
            s_z[buf][t][lj]=r_z[k];
            s_B[buf][t][lj]=r_B[k];
            s_C[buf][t][lj]=r_C[k];
        }
        __syncthreads();
        if (c+1 < NC){
            int t0 = (c+1)*ST;
            #pragma unroll
            for (int k=0;k<4;k++){
                int t = lt0 + k*16;
                int tok = b*LL + t0 + t;
                r_delta[k] = delta[(size_t)tok*DI + d0 + lj];
                r_x[k]     = xc[(size_t)tok*DI + d0 + lj];
                r_z[k]     = xz[(size_t)tok*(2*DI) + DI + d0 + lj];
                r_B[k]     = dbc[(size_t)tok*XPE + DD + lj];
                r_C[k]     = dbc[(size_t)tok*XPE + DD + DS + lj];
            }
        }
        int dj = tid >> 4;
        int t0 = c*ST;
        #pragma unroll 4
        for (int t=0;t<ST;t++){
            float dlt = s_delta[buf][t][dj];
            float xv  = s_x[buf][t][dj];
            float Bn  = s_B[buf][t][n];
            float Cn  = s_C[buf][t][n];
            float dA  = __expf(dlt*An);
            h = fmaf(dA, h, dlt*Bn*xv);
            float y = h*Cn;
            y += __shfl_xor_sync(0xffffffffu, y, 1);
            y += __shfl_xor_sync(0xffffffffu, y, 2);
            y += __shfl_xor_sync(0xffffffffu, y, 4);
            y += __shfl_xor_sync(0xffffffffu, y, 8);
            if (n == 0){
                float z  = s_z[buf][t][dj];
                float sv = y + Dd*xv;
                out[(size_t)(b*LL + t0 + t)*DI + d] = sv * z * (1.f/(1.f+__expf(-z)));
            }
        }
        __syncthreads();
    }
}

// ---------------- launcher ----------------
extern "C" void kernel_launch(void* const* d_in, const int* in_sizes, int n_in,
                              void* d_out, int out_size)
{
    const float* x       = (const float*)d_in[0];
    const float* in_w    = (const float*)d_in[1];
    const float* conv_w  = (const float*)d_in[2];
    const float* conv_b  = (const float*)d_in[3];
    const float* xproj_w = (const float*)d_in[4];
    const float* dt_w    = (const float*)d_in[5];
    const float* dt_b    = (const float*)d_in[6];
    const float* A_log   = (const float*)d_in[7];
    const float* Dp      = (const float*)d_in[8];
    const float* out_w   = (const float*)d_in[9];
    const float* norm_w  = (const float*)d_in[10];
    float* res = (float*)d_out;

    float *xn,*xz,*xc,*dbc,*delta,*y;
    cudaGetSymbolAddress((void**)&xn,    g_xn);
    cudaGetSymbolAddress((void**)&xz,    g_xz);
    cudaGetSymbolAddress((void**)&xc,    g_xc);
    cudaGetSymbolAddress((void**)&dbc,   g_dbc);
    cudaGetSymbolAddress((void**)&delta, g_delta);
    cudaGetSymbolAddress((void**)&y,     g_y);

    // residual stream lives in d_out
    cudaMemcpyAsync(res, x, (size_t)NTOK*DM*sizeof(float), cudaMemcpyDeviceToDevice, 0);

    for (int l=0;l<2;l++){
        rmsnorm_kernel<<<NTOK, 256>>>(res, norm_w + l*DM, xn);

        // xz[M=2048, N=3072] = xn[2048,768] @ in_w[3072,768]^T
        gemm_nt<0><<<dim3(2*DI/64, NTOK/128), 256>>>(
            xn, in_w + (size_t)l*2*DI*DM, nullptr, xz,
            NTOK, 2*DI, DM, DM, DM, 2*DI);

        conv_silu_kernel<<<(NTOK*DI)/256, 256>>>(xz, conv_w + l*DI*4, conv_b + l*DI, xc);

        // dbc[2048, 80] = xc[2048,1536] @ xproj_w[80,1536]^T
        gemm_nt<0><<<dim3(2, NTOK/128), 256>>>(
            xc, xproj_w + (size_t)l*XPE*DI, nullptr, dbc,
            NTOK, XPE, DI, DI, DI, XPE);

        // delta[2048,1536] = softplus(dbc[:, :48] @ dt_w[1536,48]^T + dt_b)
        gemm_nt<1><<<dim3(DI/64, NTOK/128), 256>>>(
            dbc, dt_w + (size_t)l*DI*DD, dt_b + l*DI, delta,
            NTOK, DI, DD, XPE, DD, DI);

        scan_kernel<<<BB*DI/16, 256>>>(delta, xc, dbc, xz,
                                       A_log + (size_t)l*DI*DS, Dp + l*DI, y);

        // res[2048,768] += y[2048,1536] @ out_w[768,1536]^T
        gemm_nt<2><<<dim3(DM/64, NTOK/128), 256>>>(
            y, out_w + (size_t)l*DM*DI, nullptr, res,
            NTOK, DM, DI, DI, DI, DM);
    }
}

// round 3
// speedup vs baseline: 1.2149x; 1.2149x over previous
#include <cuda_runtime.h>
#include <math.h>
#include <cstdint>

#define BB 2
#define LL 1024
#define DM 768
#define DI 1536
#define DS 16
#define DD 48
#define NTOK (BB*LL)
#define XPE 80   // D_DELTA + 2*D_STATE

// ---------------- scratch (static device globals; no allocation) ----------------
__device__ float g_xn[NTOK*DM];          // rmsnorm output
__device__ float g_xz[NTOK*2*DI];        // in_proj output (xi | z)
__device__ float g_xc[NTOK*DI];          // conv+silu output
__device__ float g_dbc[NTOK*XPE];        // xproj output (delta_raw | B | C)
__device__ float g_delta[NTOK*DI];       // softplus(dt proj)
__device__ float g_y[NTOK*DI];           // scan output (gated)

__device__ __forceinline__ float sigmoidf_(float x){ return 1.f/(1.f+__expf(-x)); }
__device__ __forceinline__ float softplus_(float v){ return v > 20.f ? v : log1pf(expf(v)); }
__device__ __forceinline__ uint32_t f2tf32(float x){
    uint32_t u; asm("cvt.rna.tf32.f32 %0, %1;" : "=r"(u) : "f"(x)); return u;
}

// ---------------- rmsnorm: one block per token ----------------
__global__ void rmsnorm_kernel(const float* __restrict__ x, const float* __restrict__ w,
                               float* __restrict__ out)
{
    int tok = blockIdx.x;
    int tid = threadIdx.x;  // 256
    const float* xr = x + (size_t)tok*DM;
    float v0 = xr[tid], v1 = xr[tid+256], v2 = xr[tid+512];
    float s = v0*v0 + v1*v1 + v2*v2;
    #pragma unroll
    for (int o=16;o>0;o>>=1) s += __shfl_xor_sync(0xffffffffu, s, o);
    __shared__ float red[8];
    if ((tid&31)==0) red[tid>>5] = s;
    __syncthreads();
    float tot = red[0]+red[1]+red[2]+red[3]+red[4]+red[5]+red[6]+red[7];
    float r = rsqrtf(tot * (1.f/768.f) + 1e-5f);
    float* o = out + (size_t)tok*DM;
    o[tid]     = w[tid]     * v0 * r;
    o[tid+256] = w[tid+256] * v1 * r;
    o[tid+512] = w[tid+512] * v2 * r;
}

// =====================================================================
// TF32 tensor-core GEMM:  C[M,N] (epi)= A[M,K] * B[N,K]^T
// Tile 128x128x32, 8 warps (2 m x 4 n), warp tile 64x32.
// Fragment-scattered smem: A frag = 1x LDS.128, B frag = 1x LDS.64, conflict-free.
// EPI: 0 = plain store, 2 = accumulate into C (residual).
// NGUARD: guard B rows / C cols against N (for N=80).
// Requires 64KB dynamic smem.
// =====================================================================
template<int EPI, bool NGUARD>
__global__ void __launch_bounds__(256)
gemm_tf32(const float* __restrict__ A, const float* __restrict__ B,
          float* __restrict__ C, int M, int N, int K,
          int lda, int ldb, int ldc)
{
    extern __shared__ float smem[];
    float* As = smem;          // [2][4096] : [k8][mt(8)][lane(32)][reg(4)]
    float* Bs = smem + 8192;   // [2][4096] : [k8][nt(16)][lane(32)][reg(2)]

    int tid  = threadIdx.x;
    int lane = tid & 31;
    int w    = tid >> 5;
    int wm   = w & 1;        // 0..1  (64 rows each)
    int wn   = w >> 1;       // 0..3  (32 cols each)
    int m0 = blockIdx.y * 128;
    int n0 = blockIdx.x * 128;

    // loader mapping: thread -> (row r, k half)
    int r  = tid >> 1;            // 0..127
    int kh = (tid & 1) * 16;      // 0 or 16

    const float* Ag = A + (size_t)(m0 + r)*lda + kh;
    const float* Bg = B + (size_t)(n0 + r)*ldb + kh;
    bool bok = (!NGUARD) || (n0 + r < N);

    float4 pa[4], pb[4];
    #pragma unroll
    for (int q=0;q<4;q++){
        pa[q] = *(const float4*)(Ag + q*4);
        pb[q] = bok ? *(const float4*)(Bg + q*4) : make_float4(0.f,0.f,0.f,0.f);
    }

    float acc[4][4][4];
    #pragma unroll
    for (int i=0;i<4;i++)
        #pragma unroll
        for (int j=0;j<4;j++)
            #pragma unroll
            for (int e=0;e<4;e++) acc[i][j][e]=0.f;

    // precomputed scatter bases (r-dependent parts)
    int a_mt  = r >> 4;                 // 0..7
    int a_g4  = r & 7;
    int a_rhi = ((r & 15) >= 8) ? 1 : 0;
    int b_nt  = r >> 3;                 // 0..15
    int b_g4  = r & 7;

    const int KT = K / 32;
    for (int kt=0; kt<KT; kt++){
        float* Ab = As + (kt&1)*4096;
        float* Bb = Bs + (kt&1)*4096;

        #pragma unroll
        for (int q=0;q<4;q++){
            float va[4] = {pa[q].x, pa[q].y, pa[q].z, pa[q].w};
            float vb[4] = {pb[q].x, pb[q].y, pb[q].z, pb[q].w};
            #pragma unroll
            for (int e=0;e<4;e++){
                int k  = kh + q*4 + e;       // 0..31
                int k8 = k >> 3;
                int t  = k & 3;
                int khi = ((k & 7) >= 4) ? 1 : 0;
                Ab[(k8*8 + a_mt)*128 + (a_g4*4 + t)*4 + a_rhi + khi*2] = __uint_as_float(f2tf32(va[e]));
                Bb[(k8*16 + b_nt)*64 + (b_g4*4 + t)*2 + khi]           = __uint_as_float(f2tf32(vb[e]));
            }
        }
        __syncthreads();

        if (kt+1 < KT){
            const float* Ag2 = Ag + (kt+1)*32;
            const float* Bg2 = Bg + (kt+1)*32;
            #pragma unroll
            for (int q=0;q<4;q++){
                pa[q] = *(const float4*)(Ag2 + q*4);
                pb[q] = bok ? *(const float4*)(Bg2 + q*4) : make_float4(0.f,0.f,0.f,0.f);
            }
        }

        #pragma unroll
        for (int k8=0;k8<4;k8++){
            uint32_t av[4][4];
            #pragma unroll
            for (int i=0;i<4;i++){
                float4 t4 = *(const float4*)&Ab[(k8*8 + wm*4 + i)*128 + lane*4];
                av[i][0]=__float_as_uint(t4.x); av[i][1]=__float_as_uint(t4.y);
                av[i][2]=__float_as_uint(t4.z); av[i][3]=__float_as_uint(t4.w);
            }
            uint32_t bv[4][2];
            #pragma unroll
            for (int j=0;j<4;j++){
                float2 t2 = *(const float2*)&Bb[(k8*16 + wn*4 + j)*64 + lane*2];
                bv[j][0]=__float_as_uint(t2.x); bv[j][1]=__float_as_uint(t2.y);
            }
            #pragma unroll
            for (int i=0;i<4;i++)
                #pragma unroll
                for (int j=0;j<4;j++){
                    asm volatile(
                        "mma.sync.aligned.m16n8k8.row.col.f32.tf32.tf32.f32 "
                        "{%0,%1,%2,%3}, {%4,%5,%6,%7}, {%8,%9}, {%0,%1,%2,%3};"
                        : "+f"(acc[i][j][0]), "+f"(acc[i][j][1]),
                          "+f"(acc[i][j][2]), "+f"(acc[i][j][3])
                        : "r"(av[i][0]), "r"(av[i][1]), "r"(av[i][2]), "r"(av[i][3]),
                          "r"(bv[j][0]), "r"(bv[j][1]));
                }
        }
        // single barrier per iter is sufficient (write buf != any in-flight read buf)
    }

    // epilogue
    int g4 = lane >> 2, t = lane & 3;
    #pragma unroll
    for (int i=0;i<4;i++){
        int row = m0 + (wm*4 + i)*16 + g4;
        #pragma unroll
        for (int j=0;j<4;j++){
            int col = n0 + (wn*4 + j)*8 + t*2;
            if (NGUARD && col >= N) continue;
            float* cp0 = C + (size_t)row*ldc + col;
            float* cp1 = C + (size_t)(row+8)*ldc + col;
            float2 lo, hi;
            lo.x = acc[i][j][0]; lo.y = acc[i][j][1];
            hi.x = acc[i][j][2]; hi.y = acc[i][j][3];
            if (EPI == 2){
                float2 o0 = *(const float2*)cp0;
                float2 o1 = *(const float2*)cp1;
                lo.x += o0.x; lo.y += o0.y;
                hi.x += o1.x; hi.y += o1.y;
            }
            *(float2*)cp0 = lo;
            *(float2*)cp1 = hi;
        }
    }
}

// ---------------- fp32 SIMT GEMM (kept for dt projection, K=48) ----------------
// C[M,N] = softplus(A[M,K] * B[N,K]^T + bias[n])
__global__ void __launch_bounds__(256)
gemm_nt_softplus(const float* __restrict__ A, const float* __restrict__ B,
                 const float* __restrict__ bias, float* __restrict__ C,
                 int M, int N, int K, int lda, int ldb, int ldc)
{
    __shared__ float As[16][132];
    __shared__ float Bs[16][68];
    int tid = threadIdx.x;
    int m0 = blockIdx.y * 128;
    int n0 = blockIdx.x * 64;
    int tx = tid & 15, ty = tid >> 4;

    float acc[8][4];
    #pragma unroll
    for (int i=0;i<8;i++)
        #pragma unroll
        for (int j=0;j<4;j++) acc[i][j]=0.f;

    int ar = tid >> 2;
    int kq = (tid & 3) * 4;

    for (int k0=0;k0<K;k0+=16) {
        #pragma unroll
        for (int i=0;i<2;i++){
            int r = ar + i*64;
            float4 v = *(const float4*)(A + (size_t)(m0+r)*lda + k0 + kq);
            As[kq+0][r]=v.x; As[kq+1][r]=v.y; As[kq+2][r]=v.z; As[kq+3][r]=v.w;
        }
        {
            int r = ar;
            float4 v = *(const float4*)(B + (size_t)(n0+r)*ldb + k0 + kq);
            Bs[kq+0][r]=v.x; Bs[kq+1][r]=v.y; Bs[kq+2][r]=v.z; Bs[kq+3][r]=v.w;
        }
        __syncthreads();
        #pragma unroll
        for (int k=0;k<16;k++){
            float4 b  = *(const float4*)&Bs[k][tx*4];
            float4 a0 = *(const float4*)&As[k][ty*8];
            float4 a1 = *(const float4*)&As[k][ty*8+4];
            float av[8] = {a0.x,a0.y,a0.z,a0.w,a1.x,a1.y,a1.z,a1.w};
            float bv[4] = {b.x,b.y,b.z,b.w};
            #pragma unroll
            for (int i=0;i<8;i++)
                #pragma unroll
                for (int j=0;j<4;j++)
                    acc[i][j] = fmaf(av[i], bv[j], acc[i][j]);
        }
        __syncthreads();
    }

    int col = n0 + tx*4;
    float b0=bias[col], b1=bias[col+1], b2=bias[col+2], b3=bias[col+3];
    #pragma unroll
    for (int i=0;i<8;i++){
        int row = m0 + ty*8 + i;
        float* cp = C + (size_t)row*ldc + col;
        float4 o;
        o.x = softplus_(acc[i][0] + b0);
        o.y = softplus_(acc[i][1] + b1);
        o.z = softplus_(acc[i][2] + b2);
        o.w = softplus_(acc[i][3] + b3);
        *(float4*)cp = o;
    }
}

// ---------------- causal depthwise conv (K=4) + SiLU ----------------
__global__ void conv_silu_kernel(const float* __restrict__ xz, const float* __restrict__ cw,
                                 const float* __restrict__ cb, float* __restrict__ xc)
{
    int idx = blockIdx.x*blockDim.x + threadIdx.x;   // NTOK*DI total
    int d = idx % DI;
    int tok = idx / DI;
    int l = tok % LL, b = tok / LL;
    float acc = cb[d];
    #pragma unroll
    for (int j=0;j<4;j++){
        int li = l - 3 + j;
        if (li >= 0) acc = fmaf(cw[d*4+j], xz[(size_t)(b*LL+li)*(2*DI) + d], acc);
    }
    xc[idx] = acc * sigmoidf_(acc);
}

// ---------------- selective scan ----------------
#define ST 64
__global__ void __launch_bounds__(256)
scan_kernel(const float* __restrict__ delta, const float* __restrict__ xc,
            const float* __restrict__ dbc, const float* __restrict__ xz,
            const float* __restrict__ A_log, const float* __restrict__ Dp,
            float* __restrict__ out)
{
    __shared__ float s_delta[2][ST][16];
    __shared__ float s_x[2][ST][16];
    __shared__ float s_z[2][ST][16];
    __shared__ float s_B[2][ST][16];
    __shared__ float s_C[2][ST][16];

    int tid = threadIdx.x;
    int g   = blockIdx.x*16 + (tid>>4);
    int n   = tid & 15;
    int b   = g / DI;
    int d   = g % DI;
    int d0  = (blockIdx.x*16) % DI;

    float An = -expf(A_log[d*DS + n]);
    float Dd = Dp[d];

    int lj = tid & 15, lt0 = tid >> 4;

    float r_delta[4], r_x[4], r_z[4], r_B[4], r_C[4];

    const int NC = LL/ST;
    {
        #pragma unroll
        for (int k=0;k<4;k++){
            int t = lt0 + k*16;
            int tok = b*LL + t;
            r_delta[k] = delta[(size_t)tok*DI + d0 + lj];
            r_x[k]     = xc[(size_t)tok*DI + d0 + lj];
            r_z[k]     = xz[(size_t)tok*(2*DI) + DI + d0 + lj];
            r_B[k]     = dbc[(size_t)tok*XPE + DD + lj];
            r_C[k]     = dbc[(size_t)tok*XPE + DD + DS + lj];
        }
    }

    float h = 0.f;
    for (int c=0;c<NC;c++){
        int buf = c & 1;
        #pragma unroll
        for (int k=0;k<4;k++){
            int t = lt0 + k*16;
            s_delta[buf][t][lj]=r_delta[k];
            s_x[buf][t][lj]=r_x[k];
            s_z[buf][t][lj]=r_z[k];
            s_B[buf][t][lj]=r_B[k];
            s_C[buf][t][lj]=r_C[k];
        }
        __syncthreads();
        if (c+1 < NC){
            int t0 = (c+1)*ST;
            #pragma unroll
            for (int k=0;k<4;k++){
                int t = lt0 + k*16;
                int tok = b*LL + t0 + t;
                r_delta[k] = delta[(size_t)tok*DI + d0 + lj];
                r_x[k]     = xc[(size_t)tok*DI + d0 + lj];
                r_z[k]     = xz[(size_t)tok*(2*DI) + DI + d0 + lj];
                r_B[k]     = dbc[(size_t)tok*XPE + DD + lj];
                r_C[k]     = dbc[(size_t)tok*XPE + DD + DS + lj];
            }
        }
        int dj = tid >> 4;
        int t0 = c*ST;
        #pragma unroll 4
        for (int t=0;t<ST;t++){
            float dlt = s_delta[buf][t][dj];
            float xv  = s_x[buf][t][dj];
            float Bn  = s_B[buf][t][n];
            float Cn  = s_C[buf][t][n];
            float dA  = __expf(dlt*An);
            h = fmaf(dA, h, dlt*Bn*xv);
            float y = h*Cn;
            y += __shfl_xor_sync(0xffffffffu, y, 1);
            y += __shfl_xor_sync(0xffffffffu, y, 2);
            y += __shfl_xor_sync(0xffffffffu, y, 4);
            y += __shfl_xor_sync(0xffffffffu, y, 8);
            if (n == 0){
                float z  = s_z[buf][t][dj];
                float sv = y + Dd*xv;
                out[(size_t)(b*LL + t0 + t)*DI + d] = sv * z * (1.f/(1.f+__expf(-z)));
            }
        }
        __syncthreads();
    }
}

// ---------------- launcher ----------------
extern "C" void kernel_launch(void* const* d_in, const int* in_sizes, int n_in,
                              void* d_out, int out_size)
{
    const float* x       = (const float*)d_in[0];
    const float* in_w    = (const float*)d_in[1];
    const float* conv_w  = (const float*)d_in[2];
    const float* conv_b  = (const float*)d_in[3];
    const float* xproj_w = (const float*)d_in[4];
    const float* dt_w    = (const float*)d_in[5];
    const float* dt_b    = (const float*)d_in[6];
    const float* A_log   = (const float*)d_in[7];
    const float* Dp      = (const float*)d_in[8];
    const float* out_w   = (const float*)d_in[9];
    const float* norm_w  = (const float*)d_in[10];
    float* res = (float*)d_out;

    float *xn,*xz,*xc,*dbc,*delta,*y;
    cudaGetSymbolAddress((void**)&xn,    g_xn);
    cudaGetSymbolAddress((void**)&xz,    g_xz);
    cudaGetSymbolAddress((void**)&xc,    g_xc);
    cudaGetSymbolAddress((void**)&dbc,   g_dbc);
    cudaGetSymbolAddress((void**)&delta, g_delta);
    cudaGetSymbolAddress((void**)&y,     g_y);

    const int SMEM = 65536;
    cudaFuncSetAttribute(gemm_tf32<0,false>, cudaFuncAttributeMaxDynamicSharedMemorySize, SMEM);
    cudaFuncSetAttribute(gemm_tf32<0,true>,  cudaFuncAttributeMaxDynamicSharedMemorySize, SMEM);
    cudaFuncSetAttribute(gemm_tf32<2,false>, cudaFuncAttributeMaxDynamicSharedMemorySize, SMEM);

    // residual stream lives in d_out
    cudaMemcpyAsync(res, x, (size_t)NTOK*DM*sizeof(float), cudaMemcpyDeviceToDevice, 0);

    for (int l=0;l<2;l++){
        rmsnorm_kernel<<<NTOK, 256>>>(res, norm_w + l*DM, xn);

        // xz[2048, 3072] = xn[2048,768] @ in_w[3072,768]^T   (tf32)
        gemm_tf32<0,false><<<dim3(2*DI/128, NTOK/128), 256, SMEM>>>(
            xn, in_w + (size_t)l*2*DI*DM, xz, NTOK, 2*DI, DM, DM, DM, 2*DI);

        conv_silu_kernel<<<(NTOK*DI)/256, 256>>>(xz, conv_w + l*DI*4, conv_b + l*DI, xc);

        // dbc[2048, 80] = xc[2048,1536] @ xproj_w[80,1536]^T   (tf32, N-guarded)
        gemm_tf32<0,true><<<dim3(1, NTOK/128), 256, SMEM>>>(
            xc, xproj_w + (size_t)l*XPE*DI, dbc, NTOK, XPE, DI, DI, DI, XPE);

        // delta[2048,1536] = softplus(dbc[:, :48] @ dt_w[1536,48]^T + dt_b)  (fp32)
        gemm_nt_softplus<<<dim3(DI/64, NTOK/128), 256>>>(
            dbc, dt_w + (size_t)l*DI*DD, dt_b + l*DI, delta,
            NTOK, DI, DD, XPE, DD, DI);

        scan_kernel<<<BB*DI/16, 256>>>(delta, xc, dbc, xz,
                                       A_log + (size_t)l*DI*DS, Dp + l*DI, y);

        // res[2048,768] += y[2048,1536] @ out_w[768,1536]^T   (tf32, accumulate)
        gemm_tf32<2,false><<<dim3(DM/128, NTOK/128), 256, SMEM>>>(
            y, out_w + (size_t)l*DM*DI, res, NTOK, DM, DI, DI, DI, DM);
    }
}

// round 4
// speedup vs baseline: 2.0963x; 1.7255x over previous
#include <cuda_runtime.h>
#include <cuda_bf16.h>
#include <math.h>
#include <cstdint>

#define BB 2
#define LL 1024
#define DM 768
#define DI 1536
#define DS 16
#define DD 48
#define NTOK (BB*LL)
#define XPE 80   // D_DELTA + 2*D_STATE

typedef __nv_bfloat16 bf16;

// ---------------- scratch (static device globals; no allocation) ----------------
__device__ bf16  gb_xn[NTOK*DM];         // rmsnorm output (bf16)
__device__ float g_xz[NTOK*2*DI];        // in_proj output (xi | z), fp32
__device__ bf16  gb_xc[NTOK*DI];         // conv+silu output (bf16)
__device__ float g_dbc[NTOK*XPE];        // xproj output (delta_raw | B | C), fp32
__device__ bf16  gb_d48[NTOK*DD];        // bf16 copy of dbc[:, :48]
__device__ float g_delta[NTOK*DI];       // softplus(dt proj), fp32
__device__ bf16  gb_y[NTOK*DI];          // scan output (gated), bf16
// bf16 weights
__device__ bf16  gb_inw[2*2*DI*DM];
__device__ bf16  gb_xpw[2*XPE*DI];
__device__ bf16  gb_dtw[2*DI*DD];
__device__ bf16  gb_ow [2*DM*DI];

__device__ __forceinline__ float sigmoidf_(float x){ return 1.f/(1.f+__expf(-x)); }
__device__ __forceinline__ float softplus_(float v){ return v > 20.f ? v : log1pf(expf(v)); }

// ---------------- f32 -> bf16 convert (vectorized x4) ----------------
__global__ void f2bf_kernel(const float* __restrict__ in, bf16* __restrict__ out, int n)
{
    int i = (blockIdx.x*256 + threadIdx.x)*4;
    if (i >= n) return;
    float4 v = *(const float4*)(in + i);
    __nv_bfloat162 lo = __floats2bfloat162_rn(v.x, v.y);
    __nv_bfloat162 hi = __floats2bfloat162_rn(v.z, v.w);
    *(__nv_bfloat162*)(out + i)     = lo;
    *(__nv_bfloat162*)(out + i + 2) = hi;
}

// ---------------- dbc[:, :48] -> bf16 ----------------
__global__ void d48_kernel(const float* __restrict__ dbc, bf16* __restrict__ out)
{
    int i = blockIdx.x*256 + threadIdx.x;    // < NTOK*DD
    int row = i / DD, col = i - row*DD;
    out[i] = __float2bfloat16(dbc[row*XPE + col]);
}

// ---------------- rmsnorm: one block per token, bf16 out ----------------
__global__ void rmsnorm_kernel(const float* __restrict__ x, const float* __restrict__ w,
                               bf16* __restrict__ out)
{
    int tok = blockIdx.x;
    int tid = threadIdx.x;  // 256
    const float* xr = x + (size_t)tok*DM;
    float v0 = xr[tid], v1 = xr[tid+256], v2 = xr[tid+512];
    float s = v0*v0 + v1*v1 + v2*v2;
    #pragma unroll
    for (int o=16;o>0;o>>=1) s += __shfl_xor_sync(0xffffffffu, s, o);
    __shared__ float red[8];
    if ((tid&31)==0) red[tid>>5] = s;
    __syncthreads();
    float tot = red[0]+red[1]+red[2]+red[3]+red[4]+red[5]+red[6]+red[7];
    float r = rsqrtf(tot * (1.f/768.f) + 1e-5f);
    bf16* o = out + (size_t)tok*DM;
    o[tid]     = __float2bfloat16(w[tid]     * v0 * r);
    o[tid+256] = __float2bfloat16(w[tid+256] * v1 * r);
    o[tid+512] = __float2bfloat16(w[tid+512] * v2 * r);
}

// =====================================================================
// BF16 tensor-core GEMM:  C[M,N] (epi)= A[M,K_total] * B[N,K_total]^T over
// k range [kbeg, kbeg+Klen) with kbeg = blockIdx.z*Klen (split-K).
// Tile 128x128x32, 8 warps (2m x 4n), warp tile 64x32, mma m16n8k16.
// Fragment-scattered smem with XOR swizzle (<=2-way STS conflicts,
// conflict-free LDS.128/LDS.64 on the consumer side). Inputs are bf16
// (pre-converted), so the hot loop has no cvt.
// EPI: 0 = store fp32, 1 = atomicAdd fp32, 2 = softplus(acc+bias[n]) fp32.
// NGUARD: guard B rows / C cols vs N (xproj N=80).
// KGUARD: zero-fill loads for k >= Klen (dt K=48).
// =====================================================================
template<int EPI, bool NGUARD, bool KGUARD>
__global__ void __launch_bounds__(256, 2)
gemm_bf16(const bf16* __restrict__ A, const bf16* __restrict__ B,
          const float* __restrict__ bias, float* __restrict__ C,
          int M, int N, int Klen, int lda, int ldb, int ldc)
{
    __shared__ uint32_t sA[2][2048];   // [stage][ (g*8+mt)*32 + laneEff ][4 regs]
    __shared__ uint32_t sB[2][2048];   // [stage][ (g*16+nt)*32 + laneEff ][2 regs]

    int tid = threadIdx.x;
    int lane = tid & 31;
    int w    = tid >> 5;
    int wm   = w & 1;        // 0..1 (64 rows)
    int wn   = w >> 1;       // 0..3 (32 cols)
    int m0 = blockIdx.y * 128;
    int n0 = blockIdx.x * 128;
    int kbeg = blockIdx.z * Klen;

    // loader mapping: thread -> (row r, k16-group g)
    int r  = tid >> 1;
    int g  = tid & 1;
    int kh = g * 16;

    const bf16* Ag = A + (size_t)(m0 + r)*lda + kbeg + kh;
    const bf16* Bg = B + (size_t)(n0 + r)*ldb + kbeg + kh;
    bool bok = (!NGUARD) || (n0 + r < N);

    int mt  = r >> 4;
    int g4  = r & 7;
    int rhi = (r >> 3) & 1;
    int nt  = r >> 3;

    uint32_t pa[8], pb[8];   // 8 bf16x2 pairs each (pair p = k kh+2p, kh+2p+1)

    auto load_tile = [&](int kt){
        int kb = kt*32 + kh;
        uint4 z4 = make_uint4(0u,0u,0u,0u);
        uint4 a0 = (!KGUARD || kb     < Klen) ? *(const uint4*)(Ag + kt*32)     : z4;
        uint4 a1 = (!KGUARD || kb + 8 < Klen) ? *(const uint4*)(Ag + kt*32 + 8) : z4;
        uint4 b0 = (bok && (!KGUARD || kb     < Klen)) ? *(const uint4*)(Bg + kt*32)     : z4;
        uint4 b1 = (bok && (!KGUARD || kb + 8 < Klen)) ? *(const uint4*)(Bg + kt*32 + 8) : z4;
        pa[0]=a0.x; pa[1]=a0.y; pa[2]=a0.z; pa[3]=a0.w;
        pa[4]=a1.x; pa[5]=a1.y; pa[6]=a1.z; pa[7]=a1.w;
        pb[0]=b0.x; pb[1]=b0.y; pb[2]=b0.z; pb[3]=b0.w;
        pb[4]=b1.x; pb[5]=b1.y; pb[6]=b1.z; pb[7]=b1.w;
    };

    float acc[4][4][4];
    #pragma unroll
    for (int i=0;i<4;i++)
        #pragma unroll
        for (int j=0;j<4;j++)
            #pragma unroll
            for (int e=0;e<4;e++) acc[i][j][e]=0.f;

    const int KT = (Klen + 31) / 32;
    load_tile(0);

    int lp = lane ^ ((lane>>3)&3);    // consumer lane permutation

    for (int kt=0; kt<KT; kt++){
        int st = kt & 1;

        #pragma unroll
        for (int p=0;p<8;p++){
            int t = p & 3, khi = p >> 2;
            int lA = g4*4 + t;  lA = lA ^ ((lA>>3)&3) ^ g;
            sA[st][((g*8  + mt)*32 + lA)*4 + rhi + 2*khi] = pa[p];
            int lB = g4*4 + t;  lB = lB ^ ((lB>>3)&3) ^ g ^ ((nt&1)<<1);
            sB[st][((g*16 + nt)*32 + lB)*2 + khi]         = pb[p];
        }
        __syncthreads();

        if (kt+1 < KT) load_tile(kt+1);

        #pragma unroll
        for (int g2=0; g2<2; g2++){
            uint32_t av[4][4];
            #pragma unroll
            for (int i=0;i<4;i++){
                int mtc = wm*4 + i;
                uint4 v = *(const uint4*)&sA[st][((g2*8 + mtc)*32 + (lp ^ g2))*4];
                av[i][0]=v.x; av[i][1]=v.y; av[i][2]=v.z; av[i][3]=v.w;
            }
            uint32_t bv[4][2];
            #pragma unroll
            for (int j=0;j<4;j++){
                int ntc = wn*4 + j;
                uint2 v = *(const uint2*)&sB[st][((g2*16 + ntc)*32 + (lp ^ g2 ^ ((ntc&1)<<1)))*2];
                bv[j][0]=v.x; bv[j][1]=v.y;
            }
            #pragma unroll
            for (int i=0;i<4;i++)
                #pragma unroll
                for (int j=0;j<4;j++){
                    asm volatile(
                        "mma.sync.aligned.m16n8k16.row.col.f32.bf16.bf16.f32 "
                        "{%0,%1,%2,%3}, {%4,%5,%6,%7}, {%8,%9}, {%0,%1,%2,%3};"
                        : "+f"(acc[i][j][0]), "+f"(acc[i][j][1]),
                          "+f"(acc[i][j][2]), "+f"(acc[i][j][3])
                        : "r"(av[i][0]), "r"(av[i][1]), "r"(av[i][2]), "r"(av[i][3]),
                          "r"(bv[j][0]), "r"(bv[j][1]));
                }
        }
        // single barrier per iteration is sufficient (see ordering argument)
    }

    // ---- epilogue (C fragment: c0,c1 = (g4, 2t..2t+1), c2,c3 = (g4+8, ..)) ----
    int g4c = lane >> 2, tc = lane & 3;
    #pragma unroll
    for (int i=0;i<4;i++){
        int row = m0 + (wm*4 + i)*16 + g4c;
        #pragma unroll
        for (int j=0;j<4;j++){
            int col = n0 + (wn*4 + j)*8 + tc*2;
            if (NGUARD && col >= N) continue;
            float* cp0 = C + (size_t)row*ldc + col;
            float* cp1 = C + (size_t)(row+8)*ldc + col;
            if (EPI == 0){
                *(float2*)cp0 = make_float2(acc[i][j][0], acc[i][j][1]);
                *(float2*)cp1 = make_float2(acc[i][j][2], acc[i][j][3]);
            } else if (EPI == 1){
                atomicAdd(cp0,   acc[i][j][0]);
                atomicAdd(cp0+1, acc[i][j][1]);
                atomicAdd(cp1,   acc[i][j][2]);
                atomicAdd(cp1+1, acc[i][j][3]);
            } else {  // EPI == 2 : softplus(acc + bias)
                float b0 = bias[col], b1 = bias[col+1];
                *(float2*)cp0 = make_float2(softplus_(acc[i][j][0]+b0), softplus_(acc[i][j][1]+b1));
                *(float2*)cp1 = make_float2(softplus_(acc[i][j][2]+b0), softplus_(acc[i][j][3]+b1));
            }
        }
    }
}

// ---------------- causal depthwise conv (K=4) + SiLU, bf16 out ----------------
__global__ void conv_silu_kernel(const float* __restrict__ xz, const float* __restrict__ cw,
                                 const float* __restrict__ cb, bf16* __restrict__ xc)
{
    int idx = blockIdx.x*blockDim.x + threadIdx.x;   // NTOK*DI total
    int d = idx % DI;
    int tok = idx / DI;
    int l = tok % LL, b = tok / LL;
    float acc = cb[d];
    #pragma unroll
    for (int j=0;j<4;j++){
        int li = l - 3 + j;
        if (li >= 0) acc = fmaf(cw[d*4+j], xz[(size_t)(b*LL+li)*(2*DI) + d], acc);
    }
    xc[idx] = __float2bfloat16(acc * sigmoidf_(acc));
}

// ---------------- selective scan (bf16 x in, bf16 y out) ----------------
#define ST 64
__global__ void __launch_bounds__(256)
scan_kernel(const float* __restrict__ delta, const bf16* __restrict__ xc,
            const float* __restrict__ dbc, const float* __restrict__ xz,
            const float* __restrict__ A_log, const float* __restrict__ Dp,
            bf16* __restrict__ out)
{
    __shared__ float s_delta[2][ST][16];
    __shared__ float s_x[2][ST][16];
    __shared__ float s_z[2][ST][16];
    __shared__ float s_B[2][ST][16];
    __shared__ float s_C[2][ST][16];

    int tid = threadIdx.x;
    int g   = blockIdx.x*16 + (tid>>4);
    int n   = tid & 15;
    int b   = g / DI;
    int d   = g % DI;
    int d0  = (blockIdx.x*16) % DI;

    float An = -expf(A_log[d*DS + n]);
    float Dd = Dp[d];

    int lj = tid & 15, lt0 = tid >> 4;

    float r_delta[4], r_x[4], r_z[4], r_B[4], r_C[4];

    const int NC = LL/ST;
    {
        #pragma unroll
        for (int k=0;k<4;k++){
            int t = lt0 + k*16;
            int tok = b*LL + t;
            r_delta[k] = delta[(size_t)tok*DI + d0 + lj];
            r_x[k]     = __bfloat162float(xc[(size_t)tok*DI + d0 + lj]);
            r_z[k]     = xz[(size_t)tok*(2*DI) + DI + d0 + lj];
            r_B[k]     = dbc[(size_t)tok*XPE + DD + lj];
            r_C[k]     = dbc[(size_t)tok*XPE + DD + DS + lj];
        }
    }

    float h = 0.f;
    for (int c=0;c<NC;c++){
        int buf = c & 1;
        #pragma unroll
        for (int k=0;k<4;k++){
            int t = lt0 + k*16;
            s_delta[buf][t][lj]=r_delta[k];
            s_x[buf][t][lj]=r_x[k];
            s_z[buf][t][lj]=r_z[k];
            s_B[buf][t][lj]=r_B[k];
            s_C[buf][t][lj]=r_C[k];
        }
        __syncthreads();
        if (c+1 < NC){
            int t0 = (c+1)*ST;
            #pragma unroll
            for (int k=0;k<4;k++){
                int t = lt0 + k*16;
                int tok = b*LL + t0 + t;
                r_delta[k] = delta[(size_t)tok*DI + d0 + lj];
                r_x[k]     = __bfloat162float(xc[(size_t)tok*DI + d0 + lj]);
                r_z[k]     = xz[(size_t)tok*(2*DI) + DI + d0 + lj];
                r_B[k]     = dbc[(size_t)tok*XPE + DD + lj];
                r_C[k]     = dbc[(size_t)tok*XPE + DD + DS + lj];
            }
        }
        int dj = tid >> 4;
        int t0 = c*ST;
        #pragma unroll 4
        for (int t=0;t<ST;t++){
            float dlt = s_delta[buf][t][dj];
            float xv  = s_x[buf][t][dj];
            float Bn  = s_B[buf][t][n];
            float Cn  = s_C[buf][t][n];
            float dA  = __expf(dlt*An);
            h = fmaf(dA, h, dlt*Bn*xv);
            float y = h*Cn;
            y += __shfl_xor_sync(0xffffffffu, y, 1);
            y += __shfl_xor_sync(0xffffffffu, y, 2);
            y += __shfl_xor_sync(0xffffffffu, y, 4);
            y += __shfl_xor_sync(0xffffffffu, y, 8);
            if (n == 0){
                float z  = s_z[buf][t][dj];
                float sv = y + Dd*xv;
                out[(size_t)(b*LL + t0 + t)*DI + d] =
                    __float2bfloat16(sv * z * (1.f/(1.f+__expf(-z))));
            }
        }
        __syncthreads();
    }
}

// ---------------- launcher ----------------
extern "C" void kernel_launch(void* const* d_in, const int* in_sizes, int n_in,
                              void* d_out, int out_size)
{
    const float* x       = (const float*)d_in[0];
    const float* in_w    = (const float*)d_in[1];
    const float* conv_w  = (const float*)d_in[2];
    const float* conv_b  = (const float*)d_in[3];
    const float* xproj_w = (const float*)d_in[4];
    const float* dt_w    = (const float*)d_in[5];
    const float* dt_b    = (const float*)d_in[6];
    const float* A_log   = (const float*)d_in[7];
    const float* Dp      = (const float*)d_in[8];
    const float* out_w   = (const float*)d_in[9];
    const float* norm_w  = (const float*)d_in[10];
    float* res = (float*)d_out;

    bf16 *xn, *xc, *d48, *y, *inw, *xpw, *dtw, *ow;
    float *xz, *dbc, *delta;
    cudaGetSymbolAddress((void**)&xn,    gb_xn);
    cudaGetSymbolAddress((void**)&xz,    g_xz);
    cudaGetSymbolAddress((void**)&xc,    gb_xc);
    cudaGetSymbolAddress((void**)&dbc,   g_dbc);
    cudaGetSymbolAddress((void**)&d48,   gb_d48);
    cudaGetSymbolAddress((void**)&delta, g_delta);
    cudaGetSymbolAddress((void**)&y,     gb_y);
    cudaGetSymbolAddress((void**)&inw,   gb_inw);
    cudaGetSymbolAddress((void**)&xpw,   gb_xpw);
    cudaGetSymbolAddress((void**)&dtw,   gb_dtw);
    cudaGetSymbolAddress((void**)&ow,    gb_ow);

    // residual stream lives in d_out
    cudaMemcpyAsync(res, x, (size_t)NTOK*DM*sizeof(float), cudaMemcpyDeviceToDevice, 0);

    // convert all weights to bf16 (both layers at once; arrays are contiguous)
    { int n = 2*2*DI*DM; f2bf_kernel<<<(n/4+255)/256, 256>>>(in_w,    inw, n); }
    { int n = 2*XPE*DI;  f2bf_kernel<<<(n/4+255)/256, 256>>>(xproj_w, xpw, n); }
    { int n = 2*DI*DD;   f2bf_kernel<<<(n/4+255)/256, 256>>>(dt_w,    dtw, n); }
    { int n = 2*DM*DI;   f2bf_kernel<<<(n/4+255)/256, 256>>>(out_w,   ow,  n); }

    for (int l=0;l<2;l++){
        rmsnorm_kernel<<<NTOK, 256>>>(res, norm_w + l*DM, xn);

        // xz[2048,3072] = xn @ in_w^T   (bf16 mma)
        gemm_bf16<0,false,false><<<dim3(2*DI/128, NTOK/128, 1), 256>>>(
            xn, inw + (size_t)l*2*DI*DM, nullptr, xz,
            NTOK, 2*DI, DM, DM, DM, 2*DI);

        conv_silu_kernel<<<(NTOK*DI)/256, 256>>>(xz, conv_w + l*DI*4, conv_b + l*DI, xc);

        // dbc[2048,80] = xc @ xproj_w^T  (split-K=8, atomic accumulate)
        cudaMemsetAsync(dbc, 0, (size_t)NTOK*XPE*sizeof(float), 0);
        gemm_bf16<1,true,false><<<dim3(1, NTOK/128, 8), 256>>>(
            xc, xpw + (size_t)l*XPE*DI, nullptr, dbc,
            NTOK, XPE, DI/8, DI, DI, XPE);

        d48_kernel<<<(NTOK*DD)/256, 256>>>(dbc, d48);

        // delta[2048,1536] = softplus(d48 @ dt_w^T + dt_b)   (bf16 mma, K=48)
        gemm_bf16<2,false,true><<<dim3(DI/128, NTOK/128, 1), 256>>>(
            d48, dtw + (size_t)l*DI*DD, dt_b + l*DI, delta,
            NTOK, DI, DD, DD, DD, DI);

        scan_kernel<<<BB*DI/16, 256>>>(delta, xc, dbc, xz,
                                       A_log + (size_t)l*DI*DS, Dp + l*DI, y);

        // res[2048,768] += y @ out_w^T   (split-K=2, atomic accumulate)
        gemm_bf16<1,false,false><<<dim3(DM/128, NTOK/128, 2), 256>>>(
            y, ow + (size_t)l*DM*DI, nullptr, res,
            NTOK, DM, DI/2, DI, DI, DM);
    }
}